// round 2
// baseline (speedup 1.0000x reference)
#include <cuda_runtime.h>

// PNN_62156766707845 — GB300 sm_103a, round 2
// out[b] = MLP( first(b) + inner(b)^2 ), first/inner = (emb(b)*Xv) . W
// FFMA2 packed (first,inner) accumulators; 4-way d-split x 2-row blocking;
// embeddings staged (pre-scaled) into double-buffered SMEM per block.

#define FDIM 39
#define EDIM 16
#define VDIM 100000
#define RPB  128          // rows per block
#define NTHR 256

// weights: [f*16+e][quarter q][dl 0..7] as f32x2(wf,wi)
// fe stride = 40 f32x2 (q at q*10 -> 80B steps, 16B aligned, banks q*20%32 distinct)
#define FE_S2     40
#define W_F2      (FDIM * EDIM * FE_S2)          // 24960 f32x2 = 199680 B
#define W_BYTES   (W_F2 * 8)
// emb double buffer: 128 rows x 20 floats each (stride 20 -> banks rg*20%32 distinct)
#define EB_S      20
#define EB_FLTS   (2 * RPB * EB_S)               // 5120 floats = 20480 B
#define XS_S      33
#define SMEM_BYTES (W_BYTES + EB_FLTS * 4 + 2 * 1024 * 4 + 4 * 32 * 4)

__device__ __forceinline__ unsigned long long pk2(float a, float b) {
    unsigned long long r;
    asm("mov.b64 %0, {%1, %2};" : "=l"(r) : "f"(a), "f"(b));
    return r;
}
__device__ __forceinline__ void unpk2(unsigned long long v, float& lo, float& hi) {
    asm("mov.b64 {%0, %1}, %2;" : "=f"(lo), "=f"(hi) : "l"(v));
}
__device__ __forceinline__ void ffma2(unsigned long long& d, unsigned long long a,
                                      unsigned long long b) {
    asm("fma.rn.f32x2 %0, %1, %2, %3;" : "=l"(d) : "l"(a), "l"(b), "l"(d));
}

extern "C" __global__ void __launch_bounds__(NTHR, 1)
pnn_kernel(const int* __restrict__ Xi, const float* __restrict__ Xv,
           const float* __restrict__ emb,
           const float* __restrict__ w_first, const float* __restrict__ w_inner,
           const float* __restrict__ lin1W, const float* __restrict__ lin1b,
           const float* __restrict__ lin2W, const float* __restrict__ lin2b,
           const float* __restrict__ lastW, const float* __restrict__ lastb,
           float* __restrict__ out, int B)
{
    extern __shared__ char smem[];
    float2* Wsm = (float2*)smem;
    float*  eb  = (float*)(smem + W_BYTES);
    float*  l1  = (float*)(smem + W_BYTES + EB_FLTS * 4);
    float*  l2  = l1 + 1024;
    float*  bb1 = l2 + 1024;
    float*  bb2 = bb1 + 32;
    float*  lw  = bb2 + 32;
    float*  lb  = lw + 32;
    float*  xs  = eb;   // reused after main loop (16896B <= 20480B)

    const int tid = threadIdx.x;

    // ---- stage merged weights (wf, wi) ----
    for (int i = tid; i < FDIM * EDIM * 32; i += NTHR) {
        int d  = i & 31;
        int fe = i >> 5;             // f*16 + e
        int f  = fe >> 4, e = fe & 15;
        float wf = w_first[(d * FDIM + f) * EDIM + e];
        float wi = w_inner[(d * FDIM + f) * EDIM + e];
        Wsm[fe * FE_S2 + (d >> 3) * 10 + (d & 7)] = make_float2(wf, wi);
    }
    for (int i = tid; i < 1024; i += NTHR) { l1[i] = lin1W[i]; l2[i] = lin2W[i]; }
    if (tid < 32) { bb1[tid] = lin1b[tid]; bb2[tid] = lin2b[tid]; lw[tid] = lastW[tid]; }
    if (tid == 0) lb[0] = lastb[0];

    // ---- compute-role mapping: quarter q of dims, rows r0 and r0+8 ----
    const int q  = tid & 3;
    const int rg = (tid >> 2) & 7;
    const int wp = tid >> 5;
    const int r0 = wp * 16 + rg;          // local row 0
    const int r1 = r0 + 8;                // local row 1

    // ---- staging-role mapping: row srow, half 'part' of the 16 floats ----
    const int srow = tid >> 1;
    const int part = tid & 1;
    const int grow = blockIdx.x * RPB + srow;
    const long long sbase = (long long)((grow < B) ? grow : (B - 1)) * FDIM;

    // stage f = 0 into buffer 0
    {
        int   idx = Xi[sbase];
        float xv  = Xv[sbase];
        const float4* p = (const float4*)emb + (long long)idx * 4 + part * 2;
        float4 a = p[0], b = p[1];
        float4* dst = (float4*)(eb + srow * EB_S + part * 8);
        dst[0] = make_float4(a.x * xv, a.y * xv, a.z * xv, a.w * xv);
        dst[1] = make_float4(b.x * xv, b.y * xv, b.z * xv, b.w * xv);
    }
    __syncthreads();

    unsigned long long acc[16];
#pragma unroll
    for (int i = 0; i < 16; i++) acc[i] = 0ULL;

    for (int f = 0; f < FDIM; f++) {
        // prefetch gather for f+1 (hidden under this f's FMAs)
        float4 pa, pb; float xvn = 0.f;
        if (f < FDIM - 1) {
            long long o = sbase + f + 1;
            int idx = Xi[o];
            xvn = Xv[o];
            const float4* p = (const float4*)emb +
                              ((long long)(f + 1) * VDIM + idx) * 4 + part * 2;
            pa = p[0]; pb = p[1];
        }

        const float*  vb = eb + (f & 1) * (RPB * EB_S);
        const float2* wb = Wsm + f * (EDIM * FE_S2) + q * 10;

#pragma unroll
        for (int eg = 0; eg < 4; eg++) {
            float4 va = *(const float4*)(vb + r0 * EB_S + eg * 4);
            float4 vc = *(const float4*)(vb + r1 * EB_S + eg * 4);
            const float* vaf = (const float*)&va;
            const float* vcf = (const float*)&vc;
#pragma unroll
            for (int e = 0; e < 4; e++) {
                const ulonglong2* wr =
                    (const ulonglong2*)(wb + (eg * 4 + e) * FE_S2);
                ulonglong2 w0 = wr[0];
                ulonglong2 w1 = wr[1];
                ulonglong2 w2 = wr[2];
                ulonglong2 w3 = wr[3];
                unsigned long long vA = pk2(vaf[e], vaf[e]);
                unsigned long long vB = pk2(vcf[e], vcf[e]);
                ffma2(acc[0], vA, w0.x); ffma2(acc[1], vA, w0.y);
                ffma2(acc[2], vA, w1.x); ffma2(acc[3], vA, w1.y);
                ffma2(acc[4], vA, w2.x); ffma2(acc[5], vA, w2.y);
                ffma2(acc[6], vA, w3.x); ffma2(acc[7], vA, w3.y);
                ffma2(acc[8],  vB, w0.x); ffma2(acc[9],  vB, w0.y);
                ffma2(acc[10], vB, w1.x); ffma2(acc[11], vB, w1.y);
                ffma2(acc[12], vB, w2.x); ffma2(acc[13], vB, w2.y);
                ffma2(acc[14], vB, w3.x); ffma2(acc[15], vB, w3.y);
            }
        }

        // write staged f+1 tile, then barrier
        if (f < FDIM - 1) {
            float* dst = eb + ((f + 1) & 1) * (RPB * EB_S) + srow * EB_S + part * 8;
            ((float4*)dst)[0] = make_float4(pa.x * xvn, pa.y * xvn, pa.z * xvn, pa.w * xvn);
            ((float4*)dst)[1] = make_float4(pb.x * xvn, pb.y * xvn, pb.z * xvn, pb.w * xvn);
        }
        __syncthreads();
    }

    // ---- epilogue: x = first + inner^2 into xs (reuses emb buffer) ----
#pragma unroll
    for (int i = 0; i < 8; i++) {
        float fo, so;
        unpk2(acc[i], fo, so);
        xs[r0 * XS_S + q * 8 + i] = fo + so * so;
    }
#pragma unroll
    for (int i = 0; i < 8; i++) {
        float fo, so;
        unpk2(acc[8 + i], fo, so);
        xs[r1 * XS_S + q * 8 + i] = fo + so * so;
    }
    __syncthreads();

    // ---- MLP: one thread per row (threads 0..127) ----
    if (tid < RPB) {
        const int g = blockIdx.x * RPB + tid;
        if (g < B) {
            const float* x = xs + tid * XS_S;
            float h1[32];
#pragma unroll
            for (int j = 0; j < 32; j++) {
                float a = bb1[j];
                const float* wrow = l1 + j * 32;
#pragma unroll
                for (int d = 0; d < 32; d++) a = fmaf(wrow[d], x[d], a);
                h1[j] = fmaxf(a, 0.0f);
            }
            float h2[32];
#pragma unroll
            for (int j = 0; j < 32; j++) {
                float a = bb2[j];
                const float* wrow = l2 + j * 32;
#pragma unroll
                for (int d = 0; d < 32; d++) a = fmaf(wrow[d], h1[d], a);
                h2[j] = fmaxf(a, 0.0f);
            }
            float a = lb[0];
#pragma unroll
            for (int j = 0; j < 32; j++) a = fmaf(lw[j], h2[j], a);
            out[g] = a;
        }
    }
}

extern "C" void kernel_launch(void* const* d_in, const int* in_sizes, int n_in,
                              void* d_out, int out_size)
{
    const int*   Xi      = (const int*)d_in[0];
    const float* Xv      = (const float*)d_in[1];
    const float* emb     = (const float*)d_in[2];
    const float* w_first = (const float*)d_in[3];
    const float* w_inner = (const float*)d_in[4];
    const float* lin1W   = (const float*)d_in[5];
    const float* lin1b   = (const float*)d_in[6];
    const float* lin2W   = (const float*)d_in[7];
    const float* lin2b   = (const float*)d_in[8];
    const float* lastW   = (const float*)d_in[9];
    const float* lastb   = (const float*)d_in[10];
    float* out = (float*)d_out;

    const int B = in_sizes[0] / FDIM;

    cudaFuncSetAttribute(pnn_kernel, cudaFuncAttributeMaxDynamicSharedMemorySize,
                         SMEM_BYTES);

    const int grid = (B + RPB - 1) / RPB;
    pnn_kernel<<<grid, NTHR, SMEM_BYTES>>>(Xi, Xv, emb, w_first, w_inner,
                                           lin1W, lin1b, lin2W, lin2b,
                                           lastW, lastb, out, B);
}

// round 4
// speedup vs baseline: 1.3991x; 1.3991x over previous
#include <cuda_runtime.h>
#include <cstdint>

// PNN_62156766707845 — GB300 sm_103a (plain sm_103 ptxas target), round 4
// 3xTF32 GEMM via mma.sync.m16n8k8 (no 'a'-suffix features needed).
// D[16384,64] = A(emb gather * Xv) @ [w_first; w_inner]^T
// then x = first + inner^2 -> 32->32->32->1 MLP -> out[b].

#define FDIM   39
#define EDIM   16
#define VDIM   100000
#define MTILE  128
#define NTHR   256
#define NCHUNK 20            // K = 624 padded to 640, 32 per chunk

// SMEM float layout
#define AP_F   4608          // A plane: 128 rows * 36
#define BP_F   2304          // B plane: 64 rows * 36
#define A_OFF  0             // [buf][plane] *AP_F   (4 planes)
#define B_OFF  (4 * AP_F)    // 18432, [buf][plane]*BP_F (4 planes)
#define L_OFF  (B_OFF + 4 * BP_F)        // 27648
#define SMEM_F (L_OFF + 2176)
#define SMEM_BYTES (SMEM_F * 4)
#define XS_S   66            // epilogue D staging stride

__device__ __forceinline__ float tf32r(float x) {
    float r;
    asm("cvt.rna.tf32.f32 %0, %1;" : "=f"(r) : "f"(x));
    return r;
}
__device__ __forceinline__ void split4(float4 v, float s, float4& h, float4& l) {
    float a = v.x * s; h.x = tf32r(a); l.x = tf32r(a - h.x);
    float b = v.y * s; h.y = tf32r(b); l.y = tf32r(b - h.y);
    float c = v.z * s; h.z = tf32r(c); l.z = tf32r(c - h.z);
    float d = v.w * s; h.w = tf32r(d); l.w = tf32r(d - h.w);
}
__device__ __forceinline__ void mma8(float* c, const uint32_t* a, const uint32_t* b) {
    asm volatile(
        "mma.sync.aligned.m16n8k8.row.col.f32.tf32.tf32.f32 "
        "{%0,%1,%2,%3}, {%4,%5,%6,%7}, {%8,%9}, {%0,%1,%2,%3};"
        : "+f"(c[0]), "+f"(c[1]), "+f"(c[2]), "+f"(c[3])
        : "r"(a[0]), "r"(a[1]), "r"(a[2]), "r"(a[3]), "r"(b[0]), "r"(b[1]));
}
__device__ __forceinline__ uint32_t fu(float x) { return __float_as_uint(x); }

extern "C" __global__ void __launch_bounds__(NTHR, 1)
pnn_kernel(const int* __restrict__ Xi, const float* __restrict__ Xv,
           const float* __restrict__ emb,
           const float* __restrict__ w_first, const float* __restrict__ w_inner,
           const float* __restrict__ lin1W, const float* __restrict__ lin1b,
           const float* __restrict__ lin2W, const float* __restrict__ lin2b,
           const float* __restrict__ lastW, const float* __restrict__ lastb,
           float* __restrict__ out, int B)
{
    extern __shared__ float sm[];
    float* l1  = sm + L_OFF;        // 1024
    float* l2  = l1 + 1024;         // 1024
    float* bb1 = l2 + 1024;         // 32
    float* bb2 = bb1 + 32;          // 32
    float* lw  = bb2 + 32;          // 32
    float* lb  = lw + 32;           // 1

    const int tid  = threadIdx.x;
    const int wid  = tid >> 5;
    const int lane = tid & 31;
    const int qr   = lane >> 2;     // 0..7
    const int qc   = lane & 3;      // 0..3
    const int RM   = (wid & 3) * 32;
    const int CN   = (wid >> 2) * 32;

    // ---- stage lin weights ----
    for (int i = tid; i < 1024; i += NTHR) { l1[i] = lin1W[i]; l2[i] = lin2W[i]; }
    if (tid < 32) { bb1[tid] = lin1b[tid]; bb2[tid] = lin2b[tid]; lw[tid] = lastW[tid]; }
    if (tid == 0) lb[0] = lastb[0];

    // ---- staging roles ----
    const int srow  = tid >> 1;          // A: row 0..127
    const int aslot = tid & 1;           // A: feature slot within chunk
    const int grow  = blockIdx.x * MTILE + srow;
    const long long rowbase = (long long)((grow < B) ? grow : 0) * FDIM;
    const int bn   = tid >> 2;           // B: n 0..63
    const int bks  = (tid & 3) * 8;      // B: k-local base {0,8,16,24}

    // ---- stage chunk 0 into buf 0 ----
    {
        // A
        const int f = aslot;
        float4 av[4]; float axv = 0.f;
        if (f < FDIM) {
            int idx = Xi[rowbase + f];
            axv = Xv[rowbase + f];
            const float4* p = (const float4*)emb + ((long long)f * VDIM + idx) * 4;
            av[0] = p[0]; av[1] = p[1]; av[2] = p[2]; av[3] = p[3];
        } else { av[0] = av[1] = av[2] = av[3] = make_float4(0, 0, 0, 0); }
        float* Ah = sm + A_OFF;
        float* Al = Ah + AP_F;
#pragma unroll
        for (int j = 0; j < 4; j++) {
            float4 h, l;
            split4(av[j], axv, h, l);
            int off = srow * 36 + aslot * 16 + j * 4;
            *(float4*)(Ah + off) = h;
            *(float4*)(Al + off) = l;
        }
        // B
        const int f2 = (bks >> 4);       // chunk 0: f = bks>>4
        const int e0 = bks & 15;
        float4 bv[2];
        {
            const float* src = (bn < 32)
                ? (w_first + ((long long)bn * FDIM + f2) * EDIM + e0)
                : (w_inner + ((long long)(bn - 32) * FDIM + f2) * EDIM + e0);
            bv[0] = ((const float4*)src)[0];
            bv[1] = ((const float4*)src)[1];
        }
        float* Bh = sm + B_OFF;
        float* Bl = Bh + BP_F;
#pragma unroll
        for (int j = 0; j < 2; j++) {
            float4 h, l;
            split4(bv[j], 1.0f, h, l);
            int off = bn * 36 + bks + j * 4;
            *(float4*)(Bh + off) = h;
            *(float4*)(Bl + off) = l;
        }
    }
    __syncthreads();

    float acc[2][4][4];
#pragma unroll
    for (int mt = 0; mt < 2; mt++)
#pragma unroll
        for (int nt = 0; nt < 4; nt++)
#pragma unroll
            for (int c = 0; c < 4; c++) acc[mt][nt][c] = 0.f;

    // ---- main loop ----
    for (int i = 0; i < NCHUNK; i++) {
        // prefetch chunk i+1 (LDG only, before compute)
        float4 av[4]; float axv = 0.f;
        float4 bv[2]; bool bok = false;
        if (i + 1 < NCHUNK) {
            const int f = 2 * (i + 1) + aslot;
            if (f < FDIM) {
                int idx = Xi[rowbase + f];
                axv = Xv[rowbase + f];
                const float4* p = (const float4*)emb + ((long long)f * VDIM + idx) * 4;
                av[0] = p[0]; av[1] = p[1]; av[2] = p[2]; av[3] = p[3];
            } else { av[0] = av[1] = av[2] = av[3] = make_float4(0, 0, 0, 0); }
            const int f2 = 2 * (i + 1) + (bks >> 4);
            if (f2 < FDIM) {
                const int e0 = bks & 15;
                const float* src = (bn < 32)
                    ? (w_first + ((long long)bn * FDIM + f2) * EDIM + e0)
                    : (w_inner + ((long long)(bn - 32) * FDIM + f2) * EDIM + e0);
                bv[0] = ((const float4*)src)[0];
                bv[1] = ((const float4*)src)[1];
                bok = true;
            }
        }

        // compute on buf i&1
        {
            const float* Ah = sm + A_OFF + (i & 1) * 2 * AP_F;
            const float* Al = Ah + AP_F;
            const float* Bh = sm + B_OFF + (i & 1) * 2 * BP_F;
            const float* Bl = Bh + BP_F;
#pragma unroll
            for (int kt = 0; kt < 4; kt++) {
                const int kb = kt * 8 + qc;
                uint32_t ah[2][4], al[2][4], bh[4][2], bl[4][2];
#pragma unroll
                for (int mt = 0; mt < 2; mt++) {
                    const int r0 = (RM + mt * 16 + qr) * 36;
                    ah[mt][0] = fu(Ah[r0 + kb]);
                    ah[mt][1] = fu(Ah[r0 + 288 + kb]);
                    ah[mt][2] = fu(Ah[r0 + kb + 4]);
                    ah[mt][3] = fu(Ah[r0 + 288 + kb + 4]);
                    al[mt][0] = fu(Al[r0 + kb]);
                    al[mt][1] = fu(Al[r0 + 288 + kb]);
                    al[mt][2] = fu(Al[r0 + kb + 4]);
                    al[mt][3] = fu(Al[r0 + 288 + kb + 4]);
                }
#pragma unroll
                for (int nt = 0; nt < 4; nt++) {
                    const int n0 = (CN + nt * 8 + qr) * 36;
                    bh[nt][0] = fu(Bh[n0 + kb]);
                    bh[nt][1] = fu(Bh[n0 + kb + 4]);
                    bl[nt][0] = fu(Bl[n0 + kb]);
                    bl[nt][1] = fu(Bl[n0 + kb + 4]);
                }
#pragma unroll
                for (int mt = 0; mt < 2; mt++)
#pragma unroll
                    for (int nt = 0; nt < 4; nt++) {
                        mma8(acc[mt][nt], ah[mt], bh[nt]);
                        mma8(acc[mt][nt], ah[mt], bl[nt]);
                        mma8(acc[mt][nt], al[mt], bh[nt]);
                    }
            }
        }

        // store chunk i+1 into buf (i+1)&1
        if (i + 1 < NCHUNK) {
            float* Ah = sm + A_OFF + ((i + 1) & 1) * 2 * AP_F;
            float* Al = Ah + AP_F;
#pragma unroll
            for (int j = 0; j < 4; j++) {
                float4 h, l;
                split4(av[j], axv, h, l);
                int off = srow * 36 + aslot * 16 + j * 4;
                *(float4*)(Ah + off) = h;
                *(float4*)(Al + off) = l;
            }
            float* Bh = sm + B_OFF + ((i + 1) & 1) * 2 * BP_F;
            float* Bl = Bh + BP_F;
#pragma unroll
            for (int j = 0; j < 2; j++) {
                float4 h, l;
                if (bok) split4(bv[j], 1.0f, h, l);
                else { h = make_float4(0, 0, 0, 0); l = h; }
                int off = bn * 36 + bks + j * 4;
                *(float4*)(Bh + off) = h;
                *(float4*)(Bl + off) = l;
            }
        }
        __syncthreads();
    }

    // ---- epilogue: write D to xs (reuse A region), combine, MLP ----
    float* xs = sm;   // [128][66]
#pragma unroll
    for (int mt = 0; mt < 2; mt++) {
        const int r0 = RM + mt * 16 + qr;
#pragma unroll
        for (int nt = 0; nt < 4; nt++) {
            const int n = CN + nt * 8 + 2 * qc;
            *(float2*)(xs + r0 * XS_S + n)       = make_float2(acc[mt][nt][0], acc[mt][nt][1]);
            *(float2*)(xs + (r0 + 8) * XS_S + n) = make_float2(acc[mt][nt][2], acc[mt][nt][3]);
        }
    }
    __syncthreads();

    // MLP: 2 threads per row
    {
        const int rr = tid >> 1;
        const int half = tid & 1;
        float* xr = xs + rr * XS_S;

        float x[32];
#pragma unroll
        for (int d = 0; d < 32; d++) {
            float s = xr[32 + d];
            x[d] = fmaf(s, s, xr[d]);
        }
        __syncwarp();

        float h[16];
#pragma unroll
        for (int jl = 0; jl < 16; jl++) {
            const int j = half * 16 + jl;
            float a = bb1[j];
            const float* wrow = l1 + j * 32;
#pragma unroll
            for (int d = 0; d < 32; d++) a = fmaf(wrow[d], x[d], a);
            h[jl] = fmaxf(a, 0.0f);
        }
        __syncwarp();
#pragma unroll
        for (int jl = 0; jl < 16; jl++) xr[half * 16 + jl] = h[jl];
        __syncwarp();

        float h1[32];
#pragma unroll
        for (int d = 0; d < 32; d++) h1[d] = xr[d];

        float h2[16];
#pragma unroll
        for (int jl = 0; jl < 16; jl++) {
            const int j = half * 16 + jl;
            float a = bb2[j];
            const float* wrow = l2 + j * 32;
#pragma unroll
            for (int d = 0; d < 32; d++) a = fmaf(wrow[d], h1[d], a);
            h2[jl] = fmaxf(a, 0.0f);
        }
        __syncwarp();
#pragma unroll
        for (int jl = 0; jl < 16; jl++) xr[half * 16 + jl] = h2[jl];
        __syncwarp();

        if (half == 0) {
            const int g = blockIdx.x * MTILE + rr;
            if (g < B) {
                float a = lb[0];
#pragma unroll
                for (int j = 0; j < 32; j++) a = fmaf(lw[j], xr[j], a);
                out[g] = a;
            }
        }
    }
}

extern "C" void kernel_launch(void* const* d_in, const int* in_sizes, int n_in,
                              void* d_out, int out_size)
{
    const int*   Xi      = (const int*)d_in[0];
    const float* Xv      = (const float*)d_in[1];
    const float* emb     = (const float*)d_in[2];
    const float* w_first = (const float*)d_in[3];
    const float* w_inner = (const float*)d_in[4];
    const float* lin1W   = (const float*)d_in[5];
    const float* lin1b   = (const float*)d_in[6];
    const float* lin2W   = (const float*)d_in[7];
    const float* lin2b   = (const float*)d_in[8];
    const float* lastW   = (const float*)d_in[9];
    const float* lastb   = (const float*)d_in[10];
    float* out = (float*)d_out;

    const int B = in_sizes[0] / FDIM;

    cudaFuncSetAttribute(pnn_kernel, cudaFuncAttributeMaxDynamicSharedMemorySize,
                         SMEM_BYTES);

    const int grid = (B + MTILE - 1) / MTILE;
    pnn_kernel<<<grid, NTHR, SMEM_BYTES>>>(Xi, Xv, emb, w_first, w_inner,
                                           lin1W, lin1b, lin2W, lin2b,
                                           lastW, lastb, out, B);
}

// round 5
// speedup vs baseline: 1.4392x; 1.0287x over previous
#include <cuda_runtime.h>
#include <cstdint>

// PNN_62156766707845 — GB300 sm_103a, round 5
// 3xTF32 mma.sync GEMM; MTILE=64, 2 CTAs/SM, paired-k LDS.64 frag layout.

#define FDIM   39
#define EDIM   16
#define VDIM   100000
#define MTILE  64
#define NTHR   256
#define NCHUNK 20            // K = 624 padded to 640

// SMEM (floats): per buffer: Ah(2560) Al(2560) Bh(2560) Bl(2560); 2 buffers
#define PLANE_F 2560         // 64 rows * 40
#define BUF_F   (4 * PLANE_F)
#define L_OFF   (2 * BUF_F)  // 20480
#define SMEM_F  (L_OFF + 2176)
#define SMEM_BYTES (SMEM_F * 4)
#define RS      40           // row stride in floats (160B: conflict-free LDS.64)
#define XS_S    66

__device__ __forceinline__ float tf32r(float x) {
    float r;
    asm("cvt.rna.tf32.f32 %0, %1;" : "=f"(r) : "f"(x));
    return r;
}
__device__ __forceinline__ void mma8(float* c, const uint32_t* a, const uint32_t* b) {
    asm volatile(
        "mma.sync.aligned.m16n8k8.row.col.f32.tf32.tf32.f32 "
        "{%0,%1,%2,%3}, {%4,%5,%6,%7}, {%8,%9}, {%0,%1,%2,%3};"
        : "+f"(c[0]), "+f"(c[1]), "+f"(c[2]), "+f"(c[3])
        : "r"(a[0]), "r"(a[1]), "r"(a[2]), "r"(a[3]), "r"(b[0]), "r"(b[1]));
}
__device__ __forceinline__ uint32_t fu(float x) { return __float_as_uint(x); }

// write 8 consecutive-k values (base k multiple of 8) in paired layout:
// positions {0,2,4,6} <- k r=0..3 ; {1,3,5,7} <- r=4..7  => two STS.128
__device__ __forceinline__ void store_pair8(float* dst, const float* v) {
    *(float4*)(dst)     = make_float4(v[0], v[4], v[1], v[5]);
    *(float4*)(dst + 4) = make_float4(v[2], v[6], v[3], v[7]);
}

extern "C" __global__ void __launch_bounds__(NTHR, 2)
pnn_kernel(const int* __restrict__ Xi, const float* __restrict__ Xv,
           const float* __restrict__ emb,
           const float* __restrict__ w_first, const float* __restrict__ w_inner,
           const float* __restrict__ lin1W, const float* __restrict__ lin1b,
           const float* __restrict__ lin2W, const float* __restrict__ lin2b,
           const float* __restrict__ lastW, const float* __restrict__ lastb,
           float* __restrict__ out, int B)
{
    extern __shared__ float sm[];
    float* l1  = sm + L_OFF;
    float* l2  = l1 + 1024;
    float* bb1 = l2 + 1024;
    float* bb2 = bb1 + 32;
    float* lw  = bb2 + 32;
    float* lb  = lw + 32;

    const int tid  = threadIdx.x;
    const int wid  = tid >> 5;
    const int lane = tid & 31;
    const int qr   = lane >> 2;
    const int qc   = lane & 3;
    const int RM   = (wid & 1) * 32;       // warp M base (0/32)
    const int CN   = (wid >> 1) * 16;      // warp N base (0..48)

    for (int i = tid; i < 1024; i += NTHR) { l1[i] = lin1W[i]; l2[i] = lin2W[i]; }
    if (tid < 32) { bb1[tid] = lin1b[tid]; bb2[tid] = lin2b[tid]; lw[tid] = lastW[tid]; }
    if (tid == 0) lb[0] = lastb[0];

    // ---- staging roles ----
    // A: 64 rows x 2 feature-slots x 2 halves = 256 threads
    const int srow  = tid >> 2;
    const int aslot = (tid >> 1) & 1;      // feature within chunk
    const int ahalf = tid & 1;             // 8-element half of the feature
    const int akt   = aslot * 2 + ahalf;   // kt index 0..3 this thread writes
    const int grow  = blockIdx.x * MTILE + srow;
    const long long rowbase = (long long)((grow < B) ? grow : 0) * FDIM;
    // B: 64 n x 4 k-octets
    const int bn  = tid >> 2;
    const int bkt = tid & 3;

    // ---- stage chunk 0 into buf 0 ----
    {
        const int f = aslot;
        float av[8]; float axv;
        {
            int idx = Xi[rowbase + f];
            axv = Xv[rowbase + f];
            const float4* p = (const float4*)emb + ((long long)f * VDIM + idx) * 4 + ahalf * 2;
            *(float4*)(av)     = p[0];
            *(float4*)(av + 4) = p[1];
        }
        float h[8], l[8];
#pragma unroll
        for (int j = 0; j < 8; j++) {
            float a = av[j] * axv;
            h[j] = tf32r(a); l[j] = tf32r(a - h[j]);
        }
        store_pair8(sm + 0 * PLANE_F + srow * RS + akt * 8, h);
        store_pair8(sm + 1 * PLANE_F + srow * RS + akt * 8, l);

        const int f2 = (bkt * 8) >> 4, e0 = (bkt * 8) & 15;
        float bv[8];
        {
            const float* src = (bn < 32)
                ? (w_first + ((long long)bn * FDIM + f2) * EDIM + e0)
                : (w_inner + ((long long)(bn - 32) * FDIM + f2) * EDIM + e0);
            *(float4*)(bv)     = ((const float4*)src)[0];
            *(float4*)(bv + 4) = ((const float4*)src)[1];
        }
#pragma unroll
        for (int j = 0; j < 8; j++) { h[j] = tf32r(bv[j]); l[j] = tf32r(bv[j] - h[j]); }
        store_pair8(sm + 2 * PLANE_F + bn * RS + bkt * 8, h);
        store_pair8(sm + 3 * PLANE_F + bn * RS + bkt * 8, l);
    }
    __syncthreads();

    float acc[2][2][4];
#pragma unroll
    for (int mt = 0; mt < 2; mt++)
#pragma unroll
        for (int nt = 0; nt < 2; nt++)
#pragma unroll
            for (int c = 0; c < 4; c++) acc[mt][nt][c] = 0.f;

    for (int i = 0; i < NCHUNK; i++) {
        // prefetch chunk i+1
        float av[8]; float axv = 0.f;
        float bv[8]; bool bok = false;
        if (i + 1 < NCHUNK) {
            const int f = 2 * (i + 1) + aslot;
            if (f < FDIM) {
                int idx = Xi[rowbase + f];
                axv = Xv[rowbase + f];
                const float4* p = (const float4*)emb + ((long long)f * VDIM + idx) * 4 + ahalf * 2;
                *(float4*)(av)     = p[0];
                *(float4*)(av + 4) = p[1];
            } else {
#pragma unroll
                for (int j = 0; j < 8; j++) av[j] = 0.f;
            }
            const int f2 = 2 * (i + 1) + ((bkt * 8) >> 4);
            if (f2 < FDIM) {
                const int e0 = (bkt * 8) & 15;
                const float* src = (bn < 32)
                    ? (w_first + ((long long)bn * FDIM + f2) * EDIM + e0)
                    : (w_inner + ((long long)(bn - 32) * FDIM + f2) * EDIM + e0);
                *(float4*)(bv)     = ((const float4*)src)[0];
                *(float4*)(bv + 4) = ((const float4*)src)[1];
                bok = true;
            }
        }

        // compute on buf i&1
        {
            const float* base = sm + (i & 1) * BUF_F;
            const float* Ah = base;
            const float* Al = base + PLANE_F;
            const float* Bh = base + 2 * PLANE_F;
            const float* Bl = base + 3 * PLANE_F;
#pragma unroll
            for (int kt = 0; kt < 4; kt++) {
                const int ko = kt * 8 + qc * 2;
                uint32_t ah[2][4], al[2][4], bh[2][2], bl[2][2];
#pragma unroll
                for (int mt = 0; mt < 2; mt++) {
                    const int ra = (RM + mt * 16 + qr) * RS + ko;
                    const int rb = ra + 8 * RS;
                    float2 hA = *(const float2*)(Ah + ra);
                    float2 hB = *(const float2*)(Ah + rb);
                    float2 lA = *(const float2*)(Al + ra);
                    float2 lB = *(const float2*)(Al + rb);
                    ah[mt][0] = fu(hA.x); ah[mt][1] = fu(hB.x);
                    ah[mt][2] = fu(hA.y); ah[mt][3] = fu(hB.y);
                    al[mt][0] = fu(lA.x); al[mt][1] = fu(lB.x);
                    al[mt][2] = fu(lA.y); al[mt][3] = fu(lB.y);
                }
#pragma unroll
                for (int nt = 0; nt < 2; nt++) {
                    const int nb = (CN + nt * 8 + qr) * RS + ko;
                    float2 hN = *(const float2*)(Bh + nb);
                    float2 lN = *(const float2*)(Bl + nb);
                    bh[nt][0] = fu(hN.x); bh[nt][1] = fu(hN.y);
                    bl[nt][0] = fu(lN.x); bl[nt][1] = fu(lN.y);
                }
                // pass-major: >=4 independent accs between same-acc reuse
                mma8(acc[0][0], ah[0], bh[0]); mma8(acc[0][1], ah[0], bh[1]);
                mma8(acc[1][0], ah[1], bh[0]); mma8(acc[1][1], ah[1], bh[1]);
                mma8(acc[0][0], ah[0], bl[0]); mma8(acc[0][1], ah[0], bl[1]);
                mma8(acc[1][0], ah[1], bl[0]); mma8(acc[1][1], ah[1], bl[1]);
                mma8(acc[0][0], al[0], bh[0]); mma8(acc[0][1], al[0], bh[1]);
                mma8(acc[1][0], al[1], bh[0]); mma8(acc[1][1], al[1], bh[1]);
            }
        }

        // store chunk i+1 into buf (i+1)&1
        if (i + 1 < NCHUNK) {
            float* base = sm + ((i + 1) & 1) * BUF_F;
            float h[8], l[8];
#pragma unroll
            for (int j = 0; j < 8; j++) {
                float a = av[j] * axv;
                h[j] = tf32r(a); l[j] = tf32r(a - h[j]);
            }
            store_pair8(base + 0 * PLANE_F + srow * RS + akt * 8, h);
            store_pair8(base + 1 * PLANE_F + srow * RS + akt * 8, l);
#pragma unroll
            for (int j = 0; j < 8; j++) {
                float v = bok ? bv[j] : 0.f;
                h[j] = tf32r(v); l[j] = tf32r(v - h[j]);
            }
            store_pair8(base + 2 * PLANE_F + bn * RS + bkt * 8, h);
            store_pair8(base + 3 * PLANE_F + bn * RS + bkt * 8, l);
        }
        __syncthreads();
    }

    // ---- epilogue ----
    float* xs = sm;   // [64][66] = 16896 floats < buffers region
#pragma unroll
    for (int mt = 0; mt < 2; mt++) {
        const int r0 = RM + mt * 16 + qr;
#pragma unroll
        for (int nt = 0; nt < 2; nt++) {
            const int n = CN + nt * 8 + 2 * qc;
            *(float2*)(xs + r0 * XS_S + n)       = make_float2(acc[mt][nt][0], acc[mt][nt][1]);
            *(float2*)(xs + (r0 + 8) * XS_S + n) = make_float2(acc[mt][nt][2], acc[mt][nt][3]);
        }
    }
    __syncthreads();

    if (tid < 2 * MTILE) {
        const int rr = tid >> 1;
        const int half = tid & 1;
        float* xr = xs + rr * XS_S;

        float x[32];
#pragma unroll
        for (int d = 0; d < 32; d++) {
            float s = xr[32 + d];
            x[d] = fmaf(s, s, xr[d]);
        }
        __syncwarp();

        float h[16];
#pragma unroll
        for (int jl = 0; jl < 16; jl++) {
            const int j = half * 16 + jl;
            float a = bb1[j];
            const float* wrow = l1 + j * 32;
#pragma unroll
            for (int d = 0; d < 32; d++) a = fmaf(wrow[d], x[d], a);
            h[jl] = fmaxf(a, 0.0f);
        }
        __syncwarp();
#pragma unroll
        for (int jl = 0; jl < 16; jl++) xr[half * 16 + jl] = h[jl];
        __syncwarp();

        float h1[32];
#pragma unroll
        for (int d = 0; d < 32; d++) h1[d] = xr[d];

        float h2[16];
#pragma unroll
        for (int jl = 0; jl < 16; jl++) {
            const int j = half * 16 + jl;
            float a = bb2[j];
            const float* wrow = l2 + j * 32;
#pragma unroll
            for (int d = 0; d < 32; d++) a = fmaf(wrow[d], h1[d], a);
            h2[jl] = fmaxf(a, 0.0f);
        }
        __syncwarp();
#pragma unroll
        for (int jl = 0; jl < 16; jl++) xr[half * 16 + jl] = h2[jl];
        __syncwarp();

        if (half == 0) {
            const int g = blockIdx.x * MTILE + rr;
            if (g < B) {
                float a = lb[0];
#pragma unroll
                for (int j = 0; j < 32; j++) a = fmaf(lw[j], xr[j], a);
                out[g] = a;
            }
        }
    }
}

extern "C" void kernel_launch(void* const* d_in, const int* in_sizes, int n_in,
                              void* d_out, int out_size)
{
    const int*   Xi      = (const int*)d_in[0];
    const float* Xv      = (const float*)d_in[1];
    const float* emb     = (const float*)d_in[2];
    const float* w_first = (const float*)d_in[3];
    const float* w_inner = (const float*)d_in[4];
    const float* lin1W   = (const float*)d_in[5];
    const float* lin1b   = (const float*)d_in[6];
    const float* lin2W   = (const float*)d_in[7];
    const float* lin2b   = (const float*)d_in[8];
    const float* lastW   = (const float*)d_in[9];
    const float* lastb   = (const float*)d_in[10];
    float* out = (float*)d_out;

    const int B = in_sizes[0] / FDIM;

    cudaFuncSetAttribute(pnn_kernel, cudaFuncAttributeMaxDynamicSharedMemorySize,
                         SMEM_BYTES);

    const int grid = (B + MTILE - 1) / MTILE;
    pnn_kernel<<<grid, NTHR, SMEM_BYTES>>>(Xi, Xv, emb, w_first, w_inner,
                                           lin1W, lin1b, lin2W, lin2b,
                                           lastW, lastb, out, B);
}

// round 6
// speedup vs baseline: 1.8456x; 1.2824x over previous
#include <cuda_runtime.h>
#include <cstdint>

// PNN_62156766707845 — GB300 sm_103a, round 6
// bf16 2-term split (3 passes), mma.sync.m16n8k16.bf16, triple-buffered
// prefetch distance 2. MTILE=64, 2 CTAs/SM.

#define FDIM   39
#define EDIM   16
#define VDIM   100000
#define MTILE  64
#define NTHR   256
#define NCHUNK 20            // K = 640 (20 x 32), features padded 39->40

// SMEM floats. One buffer: Ah,Al,Bh,Bl planes of 64 rows x 24 floats (96B)
#define RSF     24           // row stride in floats (96B)
#define PLANE_F (64 * RSF)   // 1536
#define BUF_F   (4 * PLANE_F)   // 6144 floats = 24KB
#define L_OFF   (3 * BUF_F)     // 18432
#define SMEM_F  (L_OFF + 2176)
#define SMEM_BYTES (SMEM_F * 4)
#define XS_S    66

__device__ __forceinline__ uint32_t packbf(float lo, float hi) {
    uint32_t r;
    asm("cvt.rn.bf16x2.f32 %0, %1, %2;" : "=r"(r) : "f"(hi), "f"(lo));
    return r;
}
__device__ __forceinline__ float f_lo(uint32_t u) { return __uint_as_float(u << 16); }
__device__ __forceinline__ float f_hi(uint32_t u) { return __uint_as_float(u & 0xFFFF0000u); }

__device__ __forceinline__ void mma16(float* c, const uint32_t* a, const uint32_t* b) {
    asm volatile(
        "mma.sync.aligned.m16n8k16.row.col.f32.bf16.bf16.f32 "
        "{%0,%1,%2,%3}, {%4,%5,%6,%7}, {%8,%9}, {%0,%1,%2,%3};"
        : "+f"(c[0]), "+f"(c[1]), "+f"(c[2]), "+f"(c[3])
        : "r"(a[0]), "r"(a[1]), "r"(a[2]), "r"(a[3]), "r"(b[0]), "r"(b[1]));
}

// Convert 16 scaled floats (k=0..15) into permuted hi/lo bf16x2 blocks and
// store 32B to each plane. Slot j: (x2j, x2j+1) then (x2j+8, x2j+9).
__device__ __forceinline__ void cvt_store16(float* hdst, float* ldst, const float* x) {
    uint32_t hu[8], lu[8];
#pragma unroll
    for (int j = 0; j < 4; j++) {
        float a0 = x[2 * j],     a1 = x[2 * j + 1];
        float b0 = x[2 * j + 8], b1 = x[2 * j + 9];
        uint32_t ha = packbf(a0, a1);
        uint32_t hb = packbf(b0, b1);
        hu[2 * j]     = ha;
        hu[2 * j + 1] = hb;
        lu[2 * j]     = packbf(a0 - f_lo(ha), a1 - f_hi(ha));
        lu[2 * j + 1] = packbf(b0 - f_lo(hb), b1 - f_hi(hb));
    }
    *(uint4*)(hdst)     = make_uint4(hu[0], hu[1], hu[2], hu[3]);
    *(uint4*)(hdst + 4) = make_uint4(hu[4], hu[5], hu[6], hu[7]);
    *(uint4*)(ldst)     = make_uint4(lu[0], lu[1], lu[2], lu[3]);
    *(uint4*)(ldst + 4) = make_uint4(lu[4], lu[5], lu[6], lu[7]);
}

extern "C" __global__ void __launch_bounds__(NTHR, 2)
pnn_kernel(const int* __restrict__ Xi, const float* __restrict__ Xv,
           const float* __restrict__ emb,
           const float* __restrict__ w_first, const float* __restrict__ w_inner,
           const float* __restrict__ lin1W, const float* __restrict__ lin1b,
           const float* __restrict__ lin2W, const float* __restrict__ lin2b,
           const float* __restrict__ lastW, const float* __restrict__ lastb,
           float* __restrict__ out, int B)
{
    extern __shared__ float sm[];
    float* l1  = sm + L_OFF;
    float* l2  = l1 + 1024;
    float* bb1 = l2 + 1024;
    float* bb2 = bb1 + 32;
    float* lw  = bb2 + 32;
    float* lb  = lw + 32;

    const int tid  = threadIdx.x;
    const int wid  = tid >> 5;
    const int lane = tid & 31;
    const int qr   = lane >> 2;
    const int qc   = lane & 3;
    const int RM   = (wid & 1) * 32;
    const int CN   = (wid >> 1) * 16;

    for (int i = tid; i < 1024; i += NTHR) { l1[i] = lin1W[i]; l2[i] = lin2W[i]; }
    if (tid < 32) { bb1[tid] = lin1b[tid]; bb2[tid] = lin2b[tid]; lw[tid] = lastW[tid]; }
    if (tid == 0) lb[0] = lastb[0];

    // staging roles: tid<128 -> A (row, feature-slot); tid>=128 -> B (n, feature-slot)
    const bool isA  = tid < 128;
    const int  st   = isA ? tid : (tid - 128);
    const int  srow = st >> 1;           // A row / B n
    const int  slot = st & 1;            // feature within chunk
    const int  grow = blockIdx.x * MTILE + srow;
    const long long rowbase = (long long)((grow < B) ? grow : 0) * FDIM;
    const float* bsrc_base = (srow < 32)
        ? (w_first + (long long)srow * FDIM * EDIM)
        : (w_inner + (long long)(srow - 32) * FDIM * EDIM);

    // prefetch register file (one chunk)
    float pf[16]; float pxv = 0.f;

    // ---- prologue: stage chunk 0 directly, prefetch chunk 1 ----
    {
        const int f = slot;   // chunk 0
        float x[16];
        if (isA) {
            int idx = Xi[rowbase + f];
            float xv = Xv[rowbase + f];
            const float4* p = (const float4*)emb + ((long long)f * VDIM + idx) * 4;
            float4 v0 = p[0], v1 = p[1], v2 = p[2], v3 = p[3];
            x[0]=v0.x*xv; x[1]=v0.y*xv; x[2]=v0.z*xv; x[3]=v0.w*xv;
            x[4]=v1.x*xv; x[5]=v1.y*xv; x[6]=v1.z*xv; x[7]=v1.w*xv;
            x[8]=v2.x*xv; x[9]=v2.y*xv; x[10]=v2.z*xv; x[11]=v2.w*xv;
            x[12]=v3.x*xv; x[13]=v3.y*xv; x[14]=v3.z*xv; x[15]=v3.w*xv;
            float* hd = sm + 0 * PLANE_F + srow * RSF + slot * 8;
            cvt_store16(hd, hd + PLANE_F, x);
        } else {
            const float4* p = (const float4*)(bsrc_base + (long long)f * EDIM);
            float4 v0 = p[0], v1 = p[1], v2 = p[2], v3 = p[3];
            x[0]=v0.x; x[1]=v0.y; x[2]=v0.z; x[3]=v0.w;
            x[4]=v1.x; x[5]=v1.y; x[6]=v1.z; x[7]=v1.w;
            x[8]=v2.x; x[9]=v2.y; x[10]=v2.z; x[11]=v2.w;
            x[12]=v3.x; x[13]=v3.y; x[14]=v3.z; x[15]=v3.w;
            float* hd = sm + 2 * PLANE_F + srow * RSF + slot * 8;
            cvt_store16(hd, hd + PLANE_F, x);
        }
        // prefetch chunk 1
        const int f1 = 2 + slot;
        if (isA) {
            int idx = Xi[rowbase + f1];
            pxv = Xv[rowbase + f1];
            const float4* p = (const float4*)emb + ((long long)f1 * VDIM + idx) * 4;
            *(float4*)(pf) = p[0]; *(float4*)(pf+4) = p[1];
            *(float4*)(pf+8) = p[2]; *(float4*)(pf+12) = p[3];
        } else {
            const float4* p = (const float4*)(bsrc_base + (long long)f1 * EDIM);
            *(float4*)(pf) = p[0]; *(float4*)(pf+4) = p[1];
            *(float4*)(pf+8) = p[2]; *(float4*)(pf+12) = p[3];
        }
    }
    __syncthreads();

    float acc[2][2][4];
#pragma unroll
    for (int mt = 0; mt < 2; mt++)
#pragma unroll
        for (int nt = 0; nt < 2; nt++)
#pragma unroll
            for (int c = 0; c < 4; c++) acc[mt][nt][c] = 0.f;

    for (int i = 0; i < NCHUNK; i++) {
        // 1) convert+store chunk i+1 from prefetch regs into buf (i+1)%3
        if (i + 1 < NCHUNK) {
            float* base = sm + ((i + 1) % 3) * BUF_F;
            float x[16];
            if (isA) {
#pragma unroll
                for (int j = 0; j < 16; j++) x[j] = pf[j] * pxv;
                float* hd = base + srow * RSF + slot * 8;
                cvt_store16(hd, hd + PLANE_F, x);
            } else {
#pragma unroll
                for (int j = 0; j < 16; j++) x[j] = pf[j];
                float* hd = base + 2 * PLANE_F + srow * RSF + slot * 8;
                cvt_store16(hd, hd + PLANE_F, x);
            }
        }
        // 2) LDG chunk i+2 into prefetch regs (in flight during compute)
        if (i + 2 < NCHUNK) {
            const int f = 2 * (i + 2) + slot;
            if (isA) {
                if (f < FDIM) {
                    int idx = Xi[rowbase + f];
                    pxv = Xv[rowbase + f];
                    const float4* p = (const float4*)emb + ((long long)f * VDIM + idx) * 4;
                    *(float4*)(pf) = p[0]; *(float4*)(pf+4) = p[1];
                    *(float4*)(pf+8) = p[2]; *(float4*)(pf+12) = p[3];
                } else {
                    pxv = 0.f;
#pragma unroll
                    for (int j = 0; j < 16; j++) pf[j] = 0.f;
                }
            } else {
                if (f < FDIM) {
                    const float4* p = (const float4*)(bsrc_base + (long long)f * EDIM);
                    *(float4*)(pf) = p[0]; *(float4*)(pf+4) = p[1];
                    *(float4*)(pf+8) = p[2]; *(float4*)(pf+12) = p[3];
                } else {
#pragma unroll
                    for (int j = 0; j < 16; j++) pf[j] = 0.f;
                }
            }
        }

        // 3) compute on buf i%3
        {
            const float* base = sm + (i % 3) * BUF_F;
            const float* Ah = base;
            const float* Al = base + PLANE_F;
            const float* Bh = base + 2 * PLANE_F;
            const float* Bl = base + 3 * PLANE_F;
#pragma unroll
            for (int kt = 0; kt < 2; kt++) {
                const int ko = kt * 8 + 2 * qc;
                uint32_t ah[2][4], al[2][4], bh[2][2], bl[2][2];
#pragma unroll
                for (int mt = 0; mt < 2; mt++) {
                    const int ra = (RM + mt * 16 + qr) * RSF + ko;
                    const int rb = ra + 8 * RSF;
                    uint2 uh = *(const uint2*)(Ah + ra);
                    uint2 vh = *(const uint2*)(Ah + rb);
                    uint2 ul = *(const uint2*)(Al + ra);
                    uint2 vl = *(const uint2*)(Al + rb);
                    ah[mt][0] = uh.x; ah[mt][1] = vh.x; ah[mt][2] = uh.y; ah[mt][3] = vh.y;
                    al[mt][0] = ul.x; al[mt][1] = vl.x; al[mt][2] = ul.y; al[mt][3] = vl.y;
                }
#pragma unroll
                for (int nt = 0; nt < 2; nt++) {
                    const int nb = (CN + nt * 8 + qr) * RSF + ko;
                    uint2 wh = *(const uint2*)(Bh + nb);
                    uint2 wl = *(const uint2*)(Bl + nb);
                    bh[nt][0] = wh.x; bh[nt][1] = wh.y;
                    bl[nt][0] = wl.x; bl[nt][1] = wl.y;
                }
                mma16(acc[0][0], ah[0], bh[0]); mma16(acc[0][1], ah[0], bh[1]);
                mma16(acc[1][0], ah[1], bh[0]); mma16(acc[1][1], ah[1], bh[1]);
                mma16(acc[0][0], ah[0], bl[0]); mma16(acc[0][1], ah[0], bl[1]);
                mma16(acc[1][0], ah[1], bl[0]); mma16(acc[1][1], ah[1], bl[1]);
                mma16(acc[0][0], al[0], bh[0]); mma16(acc[0][1], al[0], bh[1]);
                mma16(acc[1][0], al[1], bh[0]); mma16(acc[1][1], al[1], bh[1]);
            }
        }
        __syncthreads();
    }

    // ---- epilogue ----
    float* xs = sm;   // [64][66] floats = 16.9KB (fits in buffer region)
#pragma unroll
    for (int mt = 0; mt < 2; mt++) {
        const int r0 = RM + mt * 16 + qr;
#pragma unroll
        for (int nt = 0; nt < 2; nt++) {
            const int n = CN + nt * 8 + 2 * qc;
            *(float2*)(xs + r0 * XS_S + n)       = make_float2(acc[mt][nt][0], acc[mt][nt][1]);
            *(float2*)(xs + (r0 + 8) * XS_S + n) = make_float2(acc[mt][nt][2], acc[mt][nt][3]);
        }
    }
    __syncthreads();

    if (tid < 2 * MTILE) {
        const int rr = tid >> 1;
        const int half = tid & 1;
        float* xr = xs + rr * XS_S;

        float x[32];
#pragma unroll
        for (int d = 0; d < 32; d++) {
            float s = xr[32 + d];
            x[d] = fmaf(s, s, xr[d]);
        }
        __syncwarp();

        float h[16];
#pragma unroll
        for (int jl = 0; jl < 16; jl++) {
            const int j = half * 16 + jl;
            float a = bb1[j];
            const float* wrow = l1 + j * 32;
#pragma unroll
            for (int d = 0; d < 32; d++) a = fmaf(wrow[d], x[d], a);
            h[jl] = fmaxf(a, 0.0f);
        }
        __syncwarp();
#pragma unroll
        for (int jl = 0; jl < 16; jl++) xr[half * 16 + jl] = h[jl];
        __syncwarp();

        float h1[32];
#pragma unroll
        for (int d = 0; d < 32; d++) h1[d] = xr[d];

        float h2[16];
#pragma unroll
        for (int jl = 0; jl < 16; jl++) {
            const int j = half * 16 + jl;
            float a = bb2[j];
            const float* wrow = l2 + j * 32;
#pragma unroll
            for (int d = 0; d < 32; d++) a = fmaf(wrow[d], h1[d], a);
            h2[jl] = fmaxf(a, 0.0f);
        }
        __syncwarp();
#pragma unroll
        for (int jl = 0; jl < 16; jl++) xr[half * 16 + jl] = h2[jl];
        __syncwarp();

        if (half == 0) {
            const int g = blockIdx.x * MTILE + rr;
            if (g < B) {
                float a = lb[0];
#pragma unroll
                for (int j = 0; j < 32; j++) a = fmaf(lw[j], xr[j], a);
                out[g] = a;
            }
        }
    }
}

extern "C" void kernel_launch(void* const* d_in, const int* in_sizes, int n_in,
                              void* d_out, int out_size)
{
    const int*   Xi      = (const int*)d_in[0];
    const float* Xv      = (const float*)d_in[1];
    const float* emb     = (const float*)d_in[2];
    const float* w_first = (const float*)d_in[3];
    const float* w_inner = (const float*)d_in[4];
    const float* lin1W   = (const float*)d_in[5];
    const float* lin1b   = (const float*)d_in[6];
    const float* lin2W   = (const float*)d_in[7];
    const float* lin2b   = (const float*)d_in[8];
    const float* lastW   = (const float*)d_in[9];
    const float* lastb   = (const float*)d_in[10];
    float* out = (float*)d_out;

    const int B = in_sizes[0] / FDIM;

    cudaFuncSetAttribute(pnn_kernel, cudaFuncAttributeMaxDynamicSharedMemorySize,
                         SMEM_BYTES);

    const int grid = (B + MTILE - 1) / MTILE;
    pnn_kernel<<<grid, NTHR, SMEM_BYTES>>>(Xi, Xv, emb, w_first, w_inner,
                                           lin1W, lin1b, lin2W, lin2b,
                                           lastW, lastb, out, B);
}